// round 13
// baseline (speedup 1.0000x reference)
// Model_star_44006234915144 — lambda * ||F^T F_star||_F^2
// R13: int8 IMMA path. Pass 1: fp32 -> int8 quantize (fixed scale 127/5) with
// TRANSPOSED output q[d][n] so k (=n) is contiguous -> non-trans ldmatrix.
// Pass 2: s8 mma.sync m16n8k32 GEMM (exact int32 accum), R9 schedule shape:
// CTA 128x128, 256 thr (4m x 2n warps, warp 32x64), K-chunk 128 int8,
// 3-stage cp.async, 2 CTAs/SM, fused deterministic square-sum reduction.
#include <cuda_runtime.h>
#include <cstdint>

#define DD 2048
#define NN 16384
#define TM 128
#define TN 128
#define KCB 128                 // k bytes (int8 elems) per chunk
#define NCH (NN / KCB)          // 128
#define STG 3
#define THREADS 256
#define ASTG (TM * KCB)         // 16384 B
#define BSTG (TN * KCB)         // 16384 B
#define STGSZ (ASTG + BSTG)     // 32768
#define SMEMSZ (STG * STGSZ)    // 98304 (x2 CTAs = 192KB/SM)
#define NCTAS ((DD / TN) * (DD / TM))   // 256

#define QINV 25.4f              // 127/5
static constexpr double QS  = 1.0 / 25.4;        // dequant scale
static constexpr double QS4 = QS * QS * QS * QS; // applied once at the end

__device__ __align__(16) signed char g_Aq[(size_t)DD * NN];  // F^T  int8 [d][n]
__device__ __align__(16) signed char g_Bq[(size_t)DD * NN];  // Fs^T int8 [e][n]
__device__ float g_partials[NCTAS];
__device__ unsigned int g_count;   // zero-init; self-resets each run

__device__ __forceinline__ uint32_t smem_u32(const void* p) {
    uint32_t a;
    asm("{ .reg .u64 t; cvta.to.shared.u64 t, %1; cvt.u32.u64 %0, t; }" : "=r"(a) : "l"(p));
    return a;
}
__device__ __forceinline__ int q8(float v) {
    return __float2int_rn(fminf(fmaxf(v * QINV, -127.0f), 127.0f));
}

#define CP_ASYNC16(dst, src)                                                       \
    asm volatile("cp.async.cg.shared.global [%0], [%1], 16;"                       \
                 :: "r"(dst), "l"(src) : "memory")
#define CP_COMMIT() asm volatile("cp.async.commit_group;" ::: "memory")
#define CP_WAIT1()  asm volatile("cp.async.wait_group 1;" ::: "memory")

// non-trans ldmatrix (sm_75 baseline): 4 x m8n8.b16 tiles
#define LDSM_X4(r0, r1, r2, r3, ad)                                                \
    asm volatile("ldmatrix.sync.aligned.m8n8.x4.shared.b16 {%0,%1,%2,%3}, [%4];"   \
                 : "=r"(r0), "=r"(r1), "=r"(r2), "=r"(r3) : "r"(ad))

// s8 IMMA, exact int32 accumulation
#define MMA16832(c, a, b0, b1)                                                     \
    asm volatile("mma.sync.aligned.m16n8k32.row.col.s32.s8.s8.s32 "                \
                 "{%0,%1,%2,%3}, {%4,%5,%6,%7}, {%8,%9}, {%0,%1,%2,%3};"           \
                 : "+r"((c)[0]), "+r"((c)[1]), "+r"((c)[2]), "+r"((c)[3])          \
                 : "r"((a)[0]), "r"((a)[1]), "r"((a)[2]), "r"((a)[3]),             \
                   "r"(b0), "r"(b1))

// ---------------- pass 1: fp32 -> int8, transposed (q[d][n]) ----------------
// block: 128(n) x 128(d) tile; smem [d][n] with 132B row pitch + col-xor swizzle
__global__ void __launch_bounds__(256)
quant_kernel(const float* __restrict__ F, const float* __restrict__ Fs) {
    __shared__ signed char sq[128 * 132];
    const int n0 = blockIdx.x * 128;
    const int d0 = blockIdx.y * 128;
    const float* src = blockIdx.z ? Fs : F;
    signed char* dst = blockIdx.z ? g_Bq : g_Aq;
    const int t = threadIdx.x;
    const int l = t & 31;
    const int w8 = t >> 5;

    // read: warp w8 covers n-rows [w8*16, w8*16+16); lane covers d = 4l..4l+3
    #pragma unroll
    for (int ii = 0; ii < 4; ii++) {
        const int nl = w8 * 16 + ii * 4;
        float4 v[4];
        #pragma unroll
        for (int i = 0; i < 4; i++)
            v[i] = ((const float4*)(src + (size_t)(n0 + nl + i) * DD + d0))[l];
        const float vv[4][4] = {{v[0].x, v[0].y, v[0].z, v[0].w},
                                {v[1].x, v[1].y, v[1].z, v[1].w},
                                {v[2].x, v[2].y, v[2].z, v[2].w},
                                {v[3].x, v[3].y, v[3].z, v[3].w}};
        #pragma unroll
        for (int j = 0; j < 4; j++) {
            const int dl = 4 * l + j;
            char4 c4;
            c4.x = (signed char)q8(vv[0][j]);
            c4.y = (signed char)q8(vv[1][j]);
            c4.z = (signed char)q8(vv[2][j]);
            c4.w = (signed char)q8(vv[3][j]);
            const int col = nl ^ (((dl >> 5) & 3) << 2);     // bank swizzle
            *(char4*)&sq[dl * 132 + col] = c4;
        }
    }
    __syncthreads();

    // write: thread t -> d-row dl = t>>1, 64B half h = t&1 (coalesced per row)
    const int dl = t >> 1;
    const int h = t & 1;
    const int s = ((dl >> 5) & 3) << 2;
    uint32_t wbuf[16];
    #pragma unroll
    for (int i = 0; i < 16; i++) {
        const int col = (h * 64 + i * 4) ^ s;
        wbuf[i] = *(const uint32_t*)&sq[dl * 132 + col];
    }
    uint4* o = (uint4*)(dst + (size_t)(d0 + dl) * NN + n0 + h * 64);
    #pragma unroll
    for (int i = 0; i < 4; i++)
        o[i] = make_uint4(wbuf[4 * i], wbuf[4 * i + 1], wbuf[4 * i + 2], wbuf[4 * i + 3]);
}

// ---------------- pass 2: s8 GEMM + square-sum (R9 schedule shape) ----------
__global__ void __launch_bounds__(THREADS, 2)
gram_kernel(const float* __restrict__ lam, float* __restrict__ out) {
    extern __shared__ char smem[];
    const uint32_t sb = smem_u32(smem);
    const int t = threadIdx.x;
    const int L = t & 31;
    const int w = t >> 5;

    const int d0 = blockIdx.y * TM;
    const int e0 = blockIdx.x * TN;

    // ---- cp.async mapping: thread owns row r = t>>1, 64B half h = t&1 ----
    const int r  = t >> 1;          // 0..127
    const int h  = t & 1;
    const uint32_t rsw = (uint32_t)(r & 7) << 4;
    const signed char* pA = g_Aq + (size_t)(d0 + r) * NN + h * 64;
    const signed char* pB = g_Bq + (size_t)(e0 + r) * NN + h * 64;

    // ---- fragment smem addressing: non-trans ldmatrix, 16-row tiles ----
    const int wm = w & 3;           // 4 warps along m (32 rows each)
    const int wn = w >> 2;          // 2 warps along n (64 cols each)
    const uint32_t laneRow  = (uint32_t)(L & 15);
    const uint32_t laneByte = (uint32_t)(L >> 4) << 4;      // 0 or 16
    const uint32_t lsw      = (laneRow & 7) << 4;
    const uint32_t aRowOff  = ((uint32_t)(wm * 32) + laneRow) * 128u;
    const uint32_t bRowOff  = ((uint32_t)(wn * 64) + laneRow) * 128u;

    int acc[2][8][4];
    #pragma unroll
    for (int i = 0; i < 2; i++)
        #pragma unroll
        for (int j = 0; j < 8; j++)
            #pragma unroll
            for (int q = 0; q < 4; q++) acc[i][j][q] = 0;

    // one stage: A 16KB + B 16KB; 4+4 cp.async x 16B per thread
    #define ISSUE_AT(c, so) do {                                                   \
        uint32_t stg = sb + (so);                                                  \
        const signed char* sa = pA + (size_t)(c) * KCB;                            \
        const signed char* sbp = pB + (size_t)(c) * KCB;                           \
        _Pragma("unroll")                                                          \
        for (int j = 0; j < 4; j++) {                                              \
            uint32_t d = stg + (uint32_t)r * 128u                                  \
                       + (((uint32_t)(h * 64 + j * 16)) ^ rsw);                    \
            CP_ASYNC16(d, sa + j * 16);                                            \
        }                                                                          \
        _Pragma("unroll")                                                          \
        for (int j = 0; j < 4; j++) {                                              \
            uint32_t d = stg + ASTG + (uint32_t)r * 128u                           \
                       + (((uint32_t)(h * 64 + j * 16)) ^ rsw);                    \
            CP_ASYNC16(d, sbp + j * 16);                                           \
        }                                                                          \
    } while (0)

    ISSUE_AT(0, 0); CP_COMMIT();
    ISSUE_AT(1, STGSZ); CP_COMMIT();

    uint32_t soRead = 0;
    uint32_t soWrite = 2 * STGSZ;

    #pragma unroll 1
    for (int it = 0; it < NCH; ++it) {
        CP_WAIT1();
        __syncthreads();
        if (it + 2 < NCH) ISSUE_AT(it + 2, soWrite);
        CP_COMMIT();

        const uint32_t sA = sb + soRead;
        const uint32_t sB = sA + ASTG;

        #pragma unroll
        for (int kh = 0; kh < 4; kh++) {                 // k32 steps within 128B
            const uint32_t colOff = (((uint32_t)(kh * 32) + laneByte) ^ lsw);
            uint32_t a[2][4];
            #pragma unroll
            for (int mt = 0; mt < 2; mt++) {
                uint32_t ad = sA + aRowOff + (uint32_t)(mt * 16) * 128u + colOff;
                LDSM_X4(a[mt][0], a[mt][1], a[mt][2], a[mt][3], ad);
            }
            #pragma unroll
            for (int nt = 0; nt < 4; nt++) {
                uint32_t b0, b1, b2, b3;
                uint32_t bd = sB + bRowOff + (uint32_t)(nt * 16) * 128u + colOff;
                LDSM_X4(b0, b1, b2, b3, bd);
                #pragma unroll
                for (int mt = 0; mt < 2; mt++) {
                    MMA16832(acc[mt][nt * 2 + 0], a[mt], b0, b2);
                    MMA16832(acc[mt][nt * 2 + 1], a[mt], b1, b3);
                }
            }
        }

        soRead  += STGSZ; if (soRead  == STG * STGSZ) soRead  = 0;
        soWrite += STGSZ; if (soWrite == STG * STGSZ) soWrite = 0;
    }

    // ---------------- square-sum epilogue (deterministic) ----------------
    float s = 0.0f;
    #pragma unroll
    for (int i = 0; i < 2; i++)
        #pragma unroll
        for (int j = 0; j < 8; j++)
            #pragma unroll
            for (int q = 0; q < 4; q++) {
                float v = (float)acc[i][j][q];
                s += v * v;
            }
    #pragma unroll
    for (int o = 16; o > 0; o >>= 1) s += __shfl_xor_sync(0xFFFFFFFFu, s, o);

    __syncthreads();                       // stage buffers dead; reuse for reduction
    float* red = (float*)smem;
    if (L == 0) red[w] = s;
    __syncthreads();

    // ---- last-CTA final reduction (deterministic order, graph-replay safe) ----
    if (t == 0) {
        float tot = 0.0f;
        #pragma unroll
        for (int i = 0; i < 8; i++) tot += red[i];
        g_partials[blockIdx.y * (DD / TN) + blockIdx.x] = tot;
        __threadfence();
        unsigned int old = atomicAdd(&g_count, 1u);
        if (old == NCTAS - 1) {
            const float4* gp = (const float4*)g_partials;
            float total = 0.0f;
            #pragma unroll 8
            for (int i = 0; i < NCTAS / 4; i++) {
                float4 v = gp[i];
                total += (v.x + v.y) + (v.z + v.w);
            }
            out[0] = lam[0] * (float)((double)total * QS4);
            __threadfence();
            g_count = 0;                   // reset for next graph replay
        }
    }
}

extern "C" void kernel_launch(void* const* d_in, const int* in_sizes, int n_in,
                              void* d_out, int out_size) {
    const float* F   = (const float*)d_in[0];
    const float* Fst = (const float*)d_in[1];
    const float* lam = (const float*)d_in[2];
    (void)in_sizes; (void)n_in; (void)out_size;

    cudaFuncSetAttribute(gram_kernel, cudaFuncAttributeMaxDynamicSharedMemorySize, SMEMSZ);

    quant_kernel<<<dim3(NN / 128, DD / 128, 2), 256>>>(F, Fst);
    dim3 grid(DD / TN, DD / TM);   // (16, 16) = 256 CTAs, 2/SM
    gram_kernel<<<grid, THREADS, SMEMSZ>>>(lam, (float*)d_out);
}

// round 14
// speedup vs baseline: 2.6762x; 2.6762x over previous
// Model_star_44006234915144 — lambda * ||F^T F_star||_F^2
// R14 = R9 core (best: 452us) + cp.async issue spread across kh iterations.
// Pass 1: fp32 -> bf16 pre-convert. Pass 2: bf16 mma.sync GEMM via cp.async.cg.
// CTA 128x128, 256 thr (4m x 2n warps), KC=64, 3-stage, 2 CTAs/SM, fused
// deterministic reduction.
#include <cuda_runtime.h>
#include <cuda_bf16.h>
#include <cstdint>

#define DD 2048
#define NN 16384
#define TM 128
#define TN 128
#define KC 64
#define NCH (NN / KC)          // 256
#define STG 3
#define THREADS 256
#define ASTG (KC * TM * 2)     // 16384 B
#define BSTG (KC * TN * 2)     // 16384 B
#define STGSZ (ASTG + BSTG)    // 32768
#define SMEMSZ (STG * STGSZ)   // 98304 (x2 CTAs = 192KB/SM)
#define NCTAS ((DD / TN) * (DD / TM))   // 256

__device__ __align__(16) __nv_bfloat16 g_Abf[(size_t)NN * DD];  // F  in bf16
__device__ __align__(16) __nv_bfloat16 g_Bbf[(size_t)NN * DD];  // Fs in bf16
__device__ float g_partials[NCTAS];
__device__ unsigned int g_count;   // zero-init; self-resets each run

__device__ __forceinline__ uint32_t smem_u32(const void* p) {
    uint32_t a;
    asm("{ .reg .u64 t; cvta.to.shared.u64 t, %1; cvt.u32.u64 %0, t; }" : "=r"(a) : "l"(p));
    return a;
}
// reg = {hi: bf16(h), lo: bf16(l)}  -> memory order [l, h]
__device__ __forceinline__ uint32_t pack_bf16x2(float h, float l) {
    uint32_t r;
    asm("cvt.rn.bf16x2.f32 %0, %1, %2;" : "=r"(r) : "f"(h), "f"(l));
    return r;
}

#define CP_ASYNC16(dst, src)                                                       \
    asm volatile("cp.async.cg.shared.global [%0], [%1], 16;"                       \
                 :: "r"(dst), "l"(src) : "memory")
#define CP_COMMIT() asm volatile("cp.async.commit_group;" ::: "memory")
#define CP_WAIT1()  asm volatile("cp.async.wait_group 1;" ::: "memory")

#define LDSM_X4_T(r0, r1, r2, r3, ad)                                              \
    asm volatile("ldmatrix.sync.aligned.m8n8.x4.trans.shared.b16 {%0,%1,%2,%3}, [%4];" \
                 : "=r"(r0), "=r"(r1), "=r"(r2), "=r"(r3) : "r"(ad))

#define MMA16816(c, a, b0, b1)                                                     \
    asm volatile("mma.sync.aligned.m16n8k16.row.col.f32.bf16.bf16.f32 "            \
                 "{%0,%1,%2,%3}, {%4,%5,%6,%7}, {%8,%9}, {%0,%1,%2,%3};"           \
                 : "+f"((c)[0]), "+f"((c)[1]), "+f"((c)[2]), "+f"((c)[3])          \
                 : "r"((a)[0]), "r"((a)[1]), "r"((a)[2]), "r"((a)[3]),             \
                   "r"(b0), "r"(b1))

// ---------------- pass 1: fp32 -> bf16 (4 x float4 per thread, exact cover) ----
__global__ void __launch_bounds__(256)
cvt_kernel(const float* __restrict__ F, const float* __restrict__ Fs) {
    const float4* src = (blockIdx.y == 0) ? (const float4*)F : (const float4*)Fs;
    uint2* dst = (uint2*)((blockIdx.y == 0) ? g_Abf : g_Bbf);
    const size_t base = ((size_t)blockIdx.x * 256 + threadIdx.x) * 4;
    float4 v[4];
    #pragma unroll
    for (int j = 0; j < 4; j++) v[j] = src[base + j];
    #pragma unroll
    for (int j = 0; j < 4; j++) {
        uint2 o;
        o.x = pack_bf16x2(v[j].y, v[j].x);
        o.y = pack_bf16x2(v[j].w, v[j].z);
        dst[base + j] = o;
    }
}

// ---------------- pass 2: GEMM + square-sum ----------------
__global__ void __launch_bounds__(THREADS, 2)
gram_kernel(const float* __restrict__ lam, float* __restrict__ out) {
    extern __shared__ char smem[];
    const uint32_t sb = smem_u32(smem);
    const int t = threadIdx.x;
    const int L = t & 31;
    const int w = t >> 5;

    const int d0 = blockIdx.y * TM;
    const int e0 = blockIdx.x * TN;

    // ---- cp.async mapping: thread owns (k0 + j*16, c16) 16B slots, j=0..3 ----
    const int k0  = t >> 4;         // 0..15
    const int c16 = t & 15;         // 0..15 (16B unit within 256B row)
    const uint32_t cpsw  = (uint32_t)(k0 & 7) << 4;
    const uint32_t cpoff = ((uint32_t)c16 * 16u) ^ cpsw;
    const __nv_bfloat16* pA = g_Abf + (size_t)k0 * DD + d0 + c16 * 8;
    const __nv_bfloat16* pB = g_Bbf + (size_t)k0 * DD + e0 + c16 * 8;
    const size_t stepj = (size_t)16 * DD;   // 16 k-rows
    const size_t stepc = (size_t)KC * DD;   // one chunk

    // ---- mma fragment smem addressing (proven R7/R9 geometry) ----
    const int wm = w & 3;           // 4 warps along m (32 rows each)
    const int wn = w >> 2;          // 2 warps along n (64 cols each)
    const uint32_t kL     = (uint32_t)((L & 7) + ((L & 16) >> 1));   // 0..15
    const uint32_t rowOff = kL * 256u;
    const uint32_t swz    = (uint32_t)(L & 7) << 4;
    const uint32_t aCol   = (uint32_t)((wm * 32 + (L & 8)) * 2);
    const uint32_t bCol   = (uint32_t)((wn * 64 + (L & 8)) * 2);

    float acc[2][8][4];
    #pragma unroll
    for (int i = 0; i < 2; i++)
        #pragma unroll
        for (int j = 0; j < 8; j++)
            #pragma unroll
            for (int q = 0; q < 4; q++) acc[i][j][q] = 0.0f;

    // issue the j-th A/B pair of a stage's copies (2 x 16B per thread)
    #define ISSUE_PAIR(c, so, j) do {                                              \
        uint32_t stg = sb + (so);                                                  \
        uint32_t da = stg + (uint32_t)(k0 + (j) * 16) * 256u + cpoff;              \
        CP_ASYNC16(da, pA + (size_t)(c) * stepc + (size_t)(j) * stepj);            \
        uint32_t db = stg + ASTG + (uint32_t)(k0 + (j) * 16) * 256u + cpoff;       \
        CP_ASYNC16(db, pB + (size_t)(c) * stepc + (size_t)(j) * stepj);            \
    } while (0)

    #define ISSUE_ALL(c, so) do {                                                  \
        _Pragma("unroll")                                                          \
        for (int j = 0; j < 4; j++) ISSUE_PAIR(c, so, j);                          \
    } while (0)

    ISSUE_ALL(0, 0); CP_COMMIT();
    ISSUE_ALL(1, STGSZ); CP_COMMIT();

    uint32_t soRead = 0;            // stage offset of chunk it
    uint32_t soWrite = 2 * STGSZ;   // stage offset of chunk it+2

    #pragma unroll 1
    for (int it = 0; it < NCH; ++it) {
        CP_WAIT1();
        __syncthreads();
        // Safe: stage soWrite == stage of chunk it-1, fully consumed pre-barrier.
        const bool doIssue = (it + 2 < NCH);

        const uint32_t sA = sb + soRead;
        const uint32_t sB = sA + ASTG;

        #pragma unroll
        for (int kh = 0; kh < 4; kh++) {
            uint32_t a[2][4];
            #pragma unroll
            for (int mt = 0; mt < 2; mt++) {
                uint32_t ad = sA + (uint32_t)kh * 4096u + rowOff
                            + ((aCol + (uint32_t)mt * 32u) ^ swz);
                LDSM_X4_T(a[mt][0], a[mt][1], a[mt][2], a[mt][3], ad);
            }
            // spread chunk it+2's copies: one A/B pair per kh (MIO pressure
            // uniform over the chunk instead of bursting at the barrier)
            if (doIssue) ISSUE_PAIR(it + 2, soWrite, kh);
            #pragma unroll
            for (int nt = 0; nt < 4; nt++) {
                uint32_t b0, b1, b2, b3;
                uint32_t bd = sB + (uint32_t)kh * 4096u + rowOff
                            + ((bCol + (uint32_t)nt * 32u) ^ swz);
                LDSM_X4_T(b0, b1, b2, b3, bd);
                #pragma unroll
                for (int mt = 0; mt < 2; mt++) {
                    MMA16816(acc[mt][nt * 2 + 0], a[mt], b0, b2);
                    MMA16816(acc[mt][nt * 2 + 1], a[mt], b1, b3);
                }
            }
        }
        CP_COMMIT();   // one group per chunk; empty at tail (same ledger as R9)

        soRead  += STGSZ; if (soRead  == STG * STGSZ) soRead  = 0;
        soWrite += STGSZ; if (soWrite == STG * STGSZ) soWrite = 0;
    }

    // ---------------- square-sum epilogue (deterministic) ----------------
    float s = 0.0f;
    #pragma unroll
    for (int i = 0; i < 2; i++)
        #pragma unroll
        for (int j = 0; j < 8; j++)
            #pragma unroll
            for (int q = 0; q < 4; q++) {
                float v = acc[i][j][q];
                s += v * v;
            }
    #pragma unroll
    for (int o = 16; o > 0; o >>= 1) s += __shfl_xor_sync(0xFFFFFFFFu, s, o);

    __syncthreads();                       // stage buffers dead; reuse for reduction
    float* red = (float*)smem;
    if (L == 0) red[w] = s;
    __syncthreads();

    // ---- last-CTA final reduction (deterministic order, graph-replay safe) ----
    if (t == 0) {
        float tot = 0.0f;
        #pragma unroll
        for (int i = 0; i < 8; i++) tot += red[i];
        g_partials[blockIdx.y * (DD / TN) + blockIdx.x] = tot;
        __threadfence();
        unsigned int old = atomicAdd(&g_count, 1u);
        if (old == NCTAS - 1) {
            const float4* gp = (const float4*)g_partials;
            float total = 0.0f;
            #pragma unroll 8
            for (int i = 0; i < NCTAS / 4; i++) {
                float4 v = gp[i];
                total += (v.x + v.y) + (v.z + v.w);
            }
            out[0] = lam[0] * total;
            __threadfence();
            g_count = 0;                   // reset for next graph replay
        }
    }
}

extern "C" void kernel_launch(void* const* d_in, const int* in_sizes, int n_in,
                              void* d_out, int out_size) {
    const float* F   = (const float*)d_in[0];
    const float* Fst = (const float*)d_in[1];
    const float* lam = (const float*)d_in[2];
    (void)in_sizes; (void)n_in; (void)out_size;

    cudaFuncSetAttribute(gram_kernel, cudaFuncAttributeMaxDynamicSharedMemorySize, SMEMSZ);

    // NF4 per matrix = NN*DD/4 = 8M; 4 float4/thread, 256 thr -> 8192 blocks
    cvt_kernel<<<dim3((size_t)NN * DD / 4 / 1024, 2), 256>>>(F, Fst);
    dim3 grid(DD / TN, DD / TM);   // (16, 16) = 256 CTAs, 2/SM
    gram_kernel<<<grid, THREADS, SMEMSZ>>>(lam, (float*)d_out);
}